// round 12
// baseline (speedup 1.0000x reference)
#include <cuda_runtime.h>
#include <cuda_bf16.h>
#include <math.h>
#include <cstdint>

#define M_TOT 8192
#define NS    4096
#define DDIM  256
#define INV_T 14.285714285714286f    // 1 / 0.07
#define SH2   20.60992915555662f     // log2(e) / 0.07  (prefolded exp2 scale)

#define NTILE 64                      // 64 row-blocks of 128
#define NCTA  304                     // 2 per SM x 152 SMs (GB300)

// sim kernel: 128x128 tile, K in 4 chunks of 64 (128 B/row), 3-stage cp.async ring
#define CHUNK_BYTES   (128 * 128)            // one tile-chunk: 128 rows x 128 B
#define STAGE_BYTES   (2 * CHUNK_BYTES)      // A chunk + B chunk
#define SMEM_TOTAL    (3 * STAGE_BYTES)      // 98304 B

// Scratch (allocation-free rule: __device__ globals)
__device__ __align__(16) __nv_bfloat16 g_featb[M_TOT * DDIM];  // 4 MB
__device__ float g_acc[M_TOT];
__device__ float g_pos[NS];
__device__ unsigned g_done = 0;

// ---------------- helpers ----------------
__device__ __forceinline__ uint32_t smem_u32(const void* p) {
    uint32_t a;
    asm("{ .reg .u64 t; cvta.to.shared.u64 t, %1; cvt.u32.u64 %0, t; }" : "=r"(a) : "l"(p));
    return a;
}
#define CP16(dst, src) \
    asm volatile("cp.async.cg.shared.global [%0], [%1], 16;" :: "r"(dst), "l"(src))
#define CP_COMMIT() asm volatile("cp.async.commit_group;" ::: "memory")
#define CP_WAIT(n)  asm volatile("cp.async.wait_group %0;" :: "n"(n) : "memory")

#define LDSM4(r0, r1, r2, r3, addr) \
    asm volatile("ldmatrix.sync.aligned.m8n8.x4.shared.b16 {%0,%1,%2,%3}, [%4];" \
                 : "=r"(r0), "=r"(r1), "=r"(r2), "=r"(r3) : "r"(addr))

#define MMA16816(c0, c1, c2, c3, a0, a1, a2, a3, b0, b1) \
    asm volatile("mma.sync.aligned.m16n8k16.row.col.f32.bf16.bf16.f32 " \
                 "{%0,%1,%2,%3},{%4,%5,%6,%7},{%8,%9},{%0,%1,%2,%3};" \
                 : "+f"(c0), "+f"(c1), "+f"(c2), "+f"(c3) \
                 : "r"(a0), "r"(a1), "r"(a2), "r"(a3), "r"(b0), "r"(b1))

__device__ __forceinline__ float ex2(float x) {
    float r;
    asm("ex2.approx.ftz.f32 %0, %1;" : "=f"(r) : "f"(x));
    return r;
}

// ---------------------------------------------------------------------------
// Kernel 1: fused clean + L2-normalize + positive-pair dot (one warp per pair).
// ---------------------------------------------------------------------------
__global__ __launch_bounds__(256) void normpos_kernel(
    const float* __restrict__ z1, const float* __restrict__ z2) {
    int w = threadIdx.x >> 5, lane = threadIdx.x & 31;
    int j = blockIdx.x * 8 + w;
    const float* s1 = z1 + (size_t)j * DDIM + lane * 8;
    const float* s2 = z2 + (size_t)j * DDIM + lane * 8;
    float4 a0 = *(const float4*)s1, a1 = *(const float4*)(s1 + 4);
    float4 b0 = *(const float4*)s2, b1 = *(const float4*)(s2 + 4);
    float x1[8] = {a0.x, a0.y, a0.z, a0.w, a1.x, a1.y, a1.z, a1.w};
    float x2[8] = {b0.x, b0.y, b0.z, b0.w, b1.x, b1.y, b1.z, b1.w};
    float ss1 = 0.f, ss2 = 0.f, sd = 0.f;
#pragma unroll
    for (int i = 0; i < 8; i++) {
        if (!isfinite(x1[i])) x1[i] = 0.0f;
        if (!isfinite(x2[i])) x2[i] = 0.0f;
        ss1 = fmaf(x1[i], x1[i], ss1);
        ss2 = fmaf(x2[i], x2[i], ss2);
        sd  = fmaf(x1[i], x2[i], sd);
    }
#pragma unroll
    for (int off = 16; off; off >>= 1) {
        ss1 += __shfl_xor_sync(0xffffffffu, ss1, off);
        ss2 += __shfl_xor_sync(0xffffffffu, ss2, off);
        sd  += __shfl_xor_sync(0xffffffffu, sd, off);
    }
    float inv1 = 1.0f / fmaxf(sqrtf(ss1), 1e-12f);
    float inv2 = 1.0f / fmaxf(sqrtf(ss2), 1e-12f);
    __nv_bfloat162 o[4];
#pragma unroll
    for (int i = 0; i < 4; i++)
        o[i] = __floats2bfloat162_rn(x1[2 * i] * inv1, x1[2 * i + 1] * inv1);
    *(uint2*)(g_featb + (size_t)j * DDIM + lane * 8) = *(uint2*)&o[0];
    *(uint2*)(g_featb + (size_t)j * DDIM + lane * 8 + 4) = *(uint2*)&o[2];
#pragma unroll
    for (int i = 0; i < 4; i++)
        o[i] = __floats2bfloat162_rn(x2[2 * i] * inv2, x2[2 * i + 1] * inv2);
    *(uint2*)(g_featb + (size_t)(j + NS) * DDIM + lane * 8) = *(uint2*)&o[0];
    *(uint2*)(g_featb + (size_t)(j + NS) * DDIM + lane * 8 + 4) = *(uint2*)&o[2];
    if (lane == 0) {
        g_pos[j] = sd * inv1 * inv2;
        g_acc[j] = 0.0f;
        g_acc[j + NS] = 0.0f;
    }
}

// ---------------------------------------------------------------------------
// Kernel 2: persistent fused HMMA sim GEMM + exp + row/col sums + final loss.
// EXACT round-8 mainloop (proven 62us): 304 persistent CTAs, 128x128 tiles,
// continuous K-chunk stream through a 3-stage cp.async ring, inline-XOR
// swizzle per LDSM, no in-chunk double-buffering.
// Only addition vs round 8: last-CTA ticket computes the loss inline.
// ---------------------------------------------------------------------------
struct Frag { float c[2][8][4]; };

__device__ __forceinline__ void compute_chunk(
    uint32_t sb, int st, int warp_m, int warp_n, int lane, Frag& f) {
    int lrow = lane & 15, khalf = lane >> 4;
    uint32_t abase = sb + (uint32_t)(st * STAGE_BYTES);
    uint32_t bbase = abase + CHUNK_BYTES;
#pragma unroll
    for (int ks = 0; ks < 4; ks++) {
        int segk = 2 * ks + khalf;
        uint32_t a0[4], a1[4];
        {
            int r = warp_m * 32 + lrow;
            LDSM4(a0[0], a0[1], a0[2], a0[3], abase + r * 128 + ((segk ^ (r & 7)) << 4));
            r += 16;
            LDSM4(a1[0], a1[1], a1[2], a1[3], abase + r * 128 + ((segk ^ (r & 7)) << 4));
        }
#pragma unroll
        for (int jj = 0; jj < 4; jj++) {
            int r = warp_n * 64 + jj * 16 + lrow;
            uint32_t b0, b1, b2, b3;
            LDSM4(b0, b1, b2, b3, bbase + r * 128 + ((segk ^ (r & 7)) << 4));
            MMA16816(f.c[0][jj*2][0], f.c[0][jj*2][1], f.c[0][jj*2][2], f.c[0][jj*2][3],
                     a0[0], a0[1], a0[2], a0[3], b0, b2);
            MMA16816(f.c[0][jj*2+1][0], f.c[0][jj*2+1][1], f.c[0][jj*2+1][2], f.c[0][jj*2+1][3],
                     a0[0], a0[1], a0[2], a0[3], b1, b3);
            MMA16816(f.c[1][jj*2][0], f.c[1][jj*2][1], f.c[1][jj*2][2], f.c[1][jj*2][3],
                     a1[0], a1[1], a1[2], a1[3], b0, b2);
            MMA16816(f.c[1][jj*2+1][0], f.c[1][jj*2+1][1], f.c[1][jj*2+1][2], f.c[1][jj*2+1][3],
                     a1[0], a1[1], a1[2], a1[3], b1, b3);
        }
    }
}

__global__ __launch_bounds__(256, 2) void sim_kernel(float* __restrict__ out) {
    extern __shared__ char smem[];
    uint32_t sb = smem_u32(smem);
    int t = threadIdx.x, lane = t & 31, wid = t >> 5;
    int warp_m = wid & 3, warp_n = wid >> 2;
    int cta = blockIdx.x;

    // Contiguous tile range: first 256 CTAs get 7 tiles, rest get 6 (256*7+48*6=2080).
    int nt = 6 + (cta < 256 ? 1 : 0);
    int start = cta * 6 + (cta < 256 ? cta : 256);
    int C4 = nt * 4;

    // Decode start tile (bi, bj) by integer walk over triangle rows.
    int bi = 0, rem = start;
    while (rem >= NTILE - bi) { rem -= NTILE - bi; bi++; }
    int bj = bi + rem;

    // Per-thread load offsets (fixed): 4 x 16B segments per chunk-half.
    uint32_t doff[4]; int soff[4];
#pragma unroll
    for (int o = 0; o < 4; o++) {
        int idx = t + o * 256;
        int r = idx >> 3, seg = idx & 7;
        doff[o] = (uint32_t)(r * 128 + ((seg ^ (r & 7)) << 4));
        soff[o] = r * 512 + seg * 16;
    }

    const char* base = (const char*)g_featb;
    int lbi = bi, lbj = bj;                       // load-cursor tile
    const char* lgA = base + (size_t)lbi * 65536; // 128 rows * 512 B
    const char* lgB = base + (size_t)lbj * 65536;

    // Prologue: chunks 0 and 1 of the first tile.
#pragma unroll
    for (int o = 0; o < 4; o++) CP16(sb + doff[o], lgA + soff[o]);
#pragma unroll
    for (int o = 0; o < 4; o++) CP16(sb + CHUNK_BYTES + doff[o], lgB + soff[o]);
    CP_COMMIT();
#pragma unroll
    for (int o = 0; o < 4; o++) CP16(sb + STAGE_BYTES + doff[o], lgA + 128 + soff[o]);
#pragma unroll
    for (int o = 0; o < 4; o++) CP16(sb + STAGE_BYTES + CHUNK_BYTES + doff[o], lgB + 128 + soff[o]);
    CP_COMMIT();

    Frag f;
#pragma unroll
    for (int i = 0; i < 2; i++)
#pragma unroll
        for (int j = 0; j < 8; j++)
#pragma unroll
            for (int k = 0; k < 4; k++) f.c[i][j][k] = 0.0f;

    for (int c = 0; c < C4; c++) {
        if (c < C4 - 1) { CP_WAIT(1); } else { CP_WAIT(0); }
        __syncthreads();   // chunk c resident; all warps past compute(c-1)

        // Prefetch chunk c+2 into stage (c+2)%3 (freed by compute(c-1)).
        int pf = c + 2;
        if (pf < C4) {
            int kc = pf & 3;
            uint32_t d0 = sb + (uint32_t)((pf % 3) * STAGE_BYTES);
            const char* a = lgA + kc * 128;
            const char* b = lgB + kc * 128;
#pragma unroll
            for (int o = 0; o < 4; o++) CP16(d0 + doff[o], a + soff[o]);
#pragma unroll
            for (int o = 0; o < 4; o++) CP16(d0 + CHUNK_BYTES + doff[o], b + soff[o]);
            CP_COMMIT();
            if (kc == 3) {                      // load-cursor to next tile
                lbj++;
                if (lbj == NTILE) { lbi++; lbj = lbi; }
                lgA = base + (size_t)lbi * 65536;
                lgB = base + (size_t)lbj * 65536;
            }
        }

        compute_chunk(sb, c % 3, warp_m, warp_n, lane, f);

        if ((c & 3) == 3) {
            // ---- Epilogue for tile (bi, bj) ----
            bool diag = (bi == bj);
            int r0 = lane >> 2;
            int cq = (lane & 3) * 2;
            float rowsum[2][2] = {{0.f, 0.f}, {0.f, 0.f}};
            float colsum[8][2];
#pragma unroll
            for (int j = 0; j < 8; j++) { colsum[j][0] = 0.f; colsum[j][1] = 0.f; }

#pragma unroll
            for (int i = 0; i < 2; i++) {
                int grA = bi * 128 + warp_m * 32 + i * 16 + r0;
#pragma unroll
                for (int j = 0; j < 8; j++) {
                    int gc = bj * 128 + warp_n * 64 + j * 8 + cq;
                    float e0 = ex2(fmaf(f.c[i][j][0], SH2, -SH2));
                    float e1 = ex2(fmaf(f.c[i][j][1], SH2, -SH2));
                    float e2 = ex2(fmaf(f.c[i][j][2], SH2, -SH2));
                    float e3 = ex2(fmaf(f.c[i][j][3], SH2, -SH2));
                    if (diag) {
                        if (grA == gc)         e0 = 0.0f;
                        if (grA == gc + 1)     e1 = 0.0f;
                        if (grA + 8 == gc)     e2 = 0.0f;
                        if (grA + 8 == gc + 1) e3 = 0.0f;
                    }
                    rowsum[i][0] += e0 + e1;
                    rowsum[i][1] += e2 + e3;
                    colsum[j][0] += e0 + e2;
                    colsum[j][1] += e1 + e3;
                }
            }

#pragma unroll
            for (int i = 0; i < 2; i++)
#pragma unroll
                for (int h = 0; h < 2; h++) {
                    rowsum[i][h] += __shfl_xor_sync(0xffffffffu, rowsum[i][h], 1);
                    rowsum[i][h] += __shfl_xor_sync(0xffffffffu, rowsum[i][h], 2);
                }
            if ((lane & 3) == 0) {
#pragma unroll
                for (int i = 0; i < 2; i++) {
                    int gr = bi * 128 + warp_m * 32 + i * 16 + r0;
                    atomicAdd(&g_acc[gr], rowsum[i][0]);
                    atomicAdd(&g_acc[gr + 8], rowsum[i][1]);
                }
            }
            if (!diag) {
#pragma unroll
                for (int j = 0; j < 8; j++)
#pragma unroll
                    for (int h = 0; h < 2; h++) {
                        colsum[j][h] += __shfl_xor_sync(0xffffffffu, colsum[j][h], 4);
                        colsum[j][h] += __shfl_xor_sync(0xffffffffu, colsum[j][h], 8);
                        colsum[j][h] += __shfl_xor_sync(0xffffffffu, colsum[j][h], 16);
                    }
                if (lane < 4) {
#pragma unroll
                    for (int j = 0; j < 8; j++) {
                        int gc = bj * 128 + warp_n * 64 + j * 8 + lane * 2;
                        atomicAdd(&g_acc[gc], colsum[j][0]);
                        atomicAdd(&g_acc[gc + 1], colsum[j][1]);
                    }
                }
            }
            // advance compute cursor + reset accumulators
            bj++;
            if (bj == NTILE) { bi++; bj = bi; }
#pragma unroll
            for (int i = 0; i < 2; i++)
#pragma unroll
                for (int j = 0; j < 8; j++)
#pragma unroll
                    for (int k = 0; k < 4; k++) f.c[i][j][k] = 0.0f;
        }
    }

    // ---- Grid-completion handoff: last CTA computes the loss. ----
    __threadfence();
    __syncthreads();
    __shared__ unsigned s_ticket;
    if (t == 0) s_ticket = atomicAdd(&g_done, 1u);
    __syncthreads();
    if (s_ticket == NCTA - 1) {
        float s = 0.0f;
        for (int i = t; i < M_TOT; i += 256)
            s += INV_T + __logf(g_acc[i]) - g_pos[i & (NS - 1)] * INV_T;
#pragma unroll
        for (int off = 16; off; off >>= 1)
            s += __shfl_xor_sync(0xffffffffu, s, off);
        __shared__ float ws[8];
        if (lane == 0) ws[wid] = s;
        __syncthreads();
        if (t == 0) {
            float tot = 0.0f;
#pragma unroll
            for (int k = 0; k < 8; k++) tot += ws[k];
            out[0] = tot * (1.0f / (float)M_TOT);
            g_done = 0;   // reset for graph replay determinism
        }
    }
}

// ---------------------------------------------------------------------------
extern "C" void kernel_launch(void* const* d_in, const int* in_sizes, int n_in,
                              void* d_out, int out_size) {
    (void)in_sizes; (void)n_in; (void)out_size;
    const float* z1 = (const float*)d_in[0];
    const float* z2 = (const float*)d_in[1];
    float* out = (float*)d_out;

    cudaFuncSetAttribute(sim_kernel, cudaFuncAttributeMaxDynamicSharedMemorySize, SMEM_TOTAL);

    normpos_kernel<<<NS / 8, 256>>>(z1, z2);
    sim_kernel<<<NCTA, 256, SMEM_TOTAL>>>(out);
}

// round 13
// speedup vs baseline: 1.1285x; 1.1285x over previous
#include <cuda_runtime.h>
#include <cuda_bf16.h>
#include <math.h>
#include <cstdint>

#define M_TOT 8192
#define NS    4096
#define DDIM  256
#define INV_T 14.285714285714286f    // 1 / 0.07
#define SH2   20.60992915555662f     // log2(e) / 0.07  (prefolded exp2 scale)

#define NTILE 64                      // 64 row-blocks of 128
#define NCTA  304                     // 2 per SM x 152 SMs (GB300)

// sim kernel: 128x128 tile. A tile resident (full K=256, 4 chunk-blocks of 16KB);
// B streamed in 16KB chunks (64 cols) through a 3-stage ring.
#define BCHUNK     16384
#define A_BYTES    65536                       // 4 * 16KB chunk-blocks
#define SMEM_TOTAL (A_BYTES + 3 * BCHUNK)      // 114688 B (112 KB) -> 2 CTAs/SM

// Scratch (allocation-free rule: __device__ globals)
__device__ __align__(16) __nv_bfloat16 g_featb[M_TOT * DDIM];  // 4 MB
__device__ float g_acc[M_TOT];
__device__ float g_pos[NS];
__device__ unsigned g_done = 0;

// ---------------- helpers ----------------
__device__ __forceinline__ uint32_t smem_u32(const void* p) {
    uint32_t a;
    asm("{ .reg .u64 t; cvta.to.shared.u64 t, %1; cvt.u32.u64 %0, t; }" : "=r"(a) : "l"(p));
    return a;
}
#define CP16(dst, src) \
    asm volatile("cp.async.cg.shared.global [%0], [%1], 16;" :: "r"(dst), "l"(src))
#define CP_COMMIT() asm volatile("cp.async.commit_group;" ::: "memory")
#define CP_WAIT(n)  asm volatile("cp.async.wait_group %0;" :: "n"(n) : "memory")

#define LDSM4(r0, r1, r2, r3, addr) \
    asm volatile("ldmatrix.sync.aligned.m8n8.x4.shared.b16 {%0,%1,%2,%3}, [%4];" \
                 : "=r"(r0), "=r"(r1), "=r"(r2), "=r"(r3) : "r"(addr))

#define MMA16816(c0, c1, c2, c3, a0, a1, a2, a3, b0, b1) \
    asm volatile("mma.sync.aligned.m16n8k16.row.col.f32.bf16.bf16.f32 " \
                 "{%0,%1,%2,%3},{%4,%5,%6,%7},{%8,%9},{%0,%1,%2,%3};" \
                 : "+f"(c0), "+f"(c1), "+f"(c2), "+f"(c3) \
                 : "r"(a0), "r"(a1), "r"(a2), "r"(a3), "r"(b0), "r"(b1))

__device__ __forceinline__ float ex2(float x) {
    float r;
    asm("ex2.approx.ftz.f32 %0, %1;" : "=f"(r) : "f"(x));
    return r;
}

// ---------------------------------------------------------------------------
// Kernel 1: fused clean + L2-normalize + positive-pair dot (one warp per pair).
// ---------------------------------------------------------------------------
__global__ __launch_bounds__(256) void normpos_kernel(
    const float* __restrict__ z1, const float* __restrict__ z2) {
    int w = threadIdx.x >> 5, lane = threadIdx.x & 31;
    int j = blockIdx.x * 8 + w;
    const float* s1 = z1 + (size_t)j * DDIM + lane * 8;
    const float* s2 = z2 + (size_t)j * DDIM + lane * 8;
    float4 a0 = *(const float4*)s1, a1 = *(const float4*)(s1 + 4);
    float4 b0 = *(const float4*)s2, b1 = *(const float4*)(s2 + 4);
    float x1[8] = {a0.x, a0.y, a0.z, a0.w, a1.x, a1.y, a1.z, a1.w};
    float x2[8] = {b0.x, b0.y, b0.z, b0.w, b1.x, b1.y, b1.z, b1.w};
    float ss1 = 0.f, ss2 = 0.f, sd = 0.f;
#pragma unroll
    for (int i = 0; i < 8; i++) {
        if (!isfinite(x1[i])) x1[i] = 0.0f;
        if (!isfinite(x2[i])) x2[i] = 0.0f;
        ss1 = fmaf(x1[i], x1[i], ss1);
        ss2 = fmaf(x2[i], x2[i], ss2);
        sd  = fmaf(x1[i], x2[i], sd);
    }
#pragma unroll
    for (int off = 16; off; off >>= 1) {
        ss1 += __shfl_xor_sync(0xffffffffu, ss1, off);
        ss2 += __shfl_xor_sync(0xffffffffu, ss2, off);
        sd  += __shfl_xor_sync(0xffffffffu, sd, off);
    }
    float inv1 = 1.0f / fmaxf(sqrtf(ss1), 1e-12f);
    float inv2 = 1.0f / fmaxf(sqrtf(ss2), 1e-12f);
    __nv_bfloat162 o[4];
#pragma unroll
    for (int i = 0; i < 4; i++)
        o[i] = __floats2bfloat162_rn(x1[2 * i] * inv1, x1[2 * i + 1] * inv1);
    *(uint2*)(g_featb + (size_t)j * DDIM + lane * 8) = *(uint2*)&o[0];
    *(uint2*)(g_featb + (size_t)j * DDIM + lane * 8 + 4) = *(uint2*)&o[2];
#pragma unroll
    for (int i = 0; i < 4; i++)
        o[i] = __floats2bfloat162_rn(x2[2 * i] * inv2, x2[2 * i + 1] * inv2);
    *(uint2*)(g_featb + (size_t)(j + NS) * DDIM + lane * 8) = *(uint2*)&o[0];
    *(uint2*)(g_featb + (size_t)(j + NS) * DDIM + lane * 8 + 4) = *(uint2*)&o[2];
    if (lane == 0) {
        g_pos[j] = sd * inv1 * inv2;
        g_acc[j] = 0.0f;
        g_acc[j + NS] = 0.0f;
    }
}

// ---------------------------------------------------------------------------
// Kernel 2: persistent fused HMMA sim GEMM + exp + row/col sums + final loss.
// 304 persistent CTAs over 2080 upper-triangle 128x128 tiles (contiguous runs).
// Per bi-segment of a run: full A tile (64KB, all K) loaded ONCE into a
// resident smem region; only B chunks (16KB = 64 cols) stream through a
// 3-stage cp.async ring. Halves L2 traffic and load-issue vs A+B streaming.
// Mainloop compute body identical to the proven round-8 kernel.
// Last CTA (ticket counter) computes the scalar loss inline.
// ---------------------------------------------------------------------------
struct Frag { float c[2][8][4]; };

__device__ __forceinline__ void compute_chunk(
    uint32_t abase, uint32_t bbase, int warp_m, int warp_n, int lane, Frag& f) {
    int lrow = lane & 15, khalf = lane >> 4;
#pragma unroll
    for (int ks = 0; ks < 4; ks++) {
        int segk = 2 * ks + khalf;
        uint32_t a0[4], a1[4];
        {
            int r = warp_m * 32 + lrow;
            LDSM4(a0[0], a0[1], a0[2], a0[3], abase + r * 128 + ((segk ^ (r & 7)) << 4));
            r += 16;
            LDSM4(a1[0], a1[1], a1[2], a1[3], abase + r * 128 + ((segk ^ (r & 7)) << 4));
        }
#pragma unroll
        for (int jj = 0; jj < 4; jj++) {
            int r = warp_n * 64 + jj * 16 + lrow;
            uint32_t b0, b1, b2, b3;
            LDSM4(b0, b1, b2, b3, bbase + r * 128 + ((segk ^ (r & 7)) << 4));
            MMA16816(f.c[0][jj*2][0], f.c[0][jj*2][1], f.c[0][jj*2][2], f.c[0][jj*2][3],
                     a0[0], a0[1], a0[2], a0[3], b0, b2);
            MMA16816(f.c[0][jj*2+1][0], f.c[0][jj*2+1][1], f.c[0][jj*2+1][2], f.c[0][jj*2+1][3],
                     a0[0], a0[1], a0[2], a0[3], b1, b3);
            MMA16816(f.c[1][jj*2][0], f.c[1][jj*2][1], f.c[1][jj*2][2], f.c[1][jj*2][3],
                     a1[0], a1[1], a1[2], a1[3], b0, b2);
            MMA16816(f.c[1][jj*2+1][0], f.c[1][jj*2+1][1], f.c[1][jj*2+1][2], f.c[1][jj*2+1][3],
                     a1[0], a1[1], a1[2], a1[3], b1, b3);
        }
    }
}

__global__ __launch_bounds__(256, 2) void sim_kernel(float* __restrict__ out) {
    extern __shared__ char smem[];
    uint32_t sb  = smem_u32(smem);        // A resident region (64 KB)
    uint32_t sbB = sb + A_BYTES;          // B ring (3 x 16 KB)
    int t = threadIdx.x, lane = t & 31, wid = t >> 5;
    int warp_m = wid & 3, warp_n = wid >> 2;
    int cta = blockIdx.x;

    // Contiguous tile range: first 256 CTAs get 7 tiles, rest get 6 (256*7+48*6=2080).
    int nt = 6 + (cta < 256 ? 1 : 0);
    int start = cta * 6 + (cta < 256 ? cta : 256);

    // Decode start tile (bi, bj) by integer walk over triangle rows.
    int bi = 0, rem = start;
    while (rem >= NTILE - bi) { rem -= NTILE - bi; bi++; }
    int bj = bi + rem;

    // Per-thread B-chunk offsets: 4 x 16B segments (1024 segs over 256 threads).
    uint32_t doffB[4]; int soffB[4];
#pragma unroll
    for (int o = 0; o < 4; o++) {
        int idx = t + o * 256;
        int r = idx >> 3, seg = idx & 7;
        doffB[o] = (uint32_t)(r * 128 + ((seg ^ (r & 7)) << 4));
        soffB[o] = r * 512 + seg * 16;
    }
    // Per-thread A offsets: 16 x 16B segments (4096 segs = 64 KB over 4 chunk-blocks).
    uint32_t doffA[16]; int soffA[16];
#pragma unroll
    for (int o = 0; o < 16; o++) {
        int idx = t + o * 256;           // 0..4095
        int ch = idx >> 10;              // K-chunk block 0..3
        int i1 = idx & 1023;
        int r = i1 >> 3, seg = i1 & 7;
        doffA[o] = (uint32_t)(ch * BCHUNK + r * 128 + ((seg ^ (r & 7)) << 4));
        soffA[o] = r * 512 + ch * 128 + seg * 16;
    }

    const char* base = (const char*)g_featb;

    Frag f;
#pragma unroll
    for (int i = 0; i < 2; i++)
#pragma unroll
        for (int j = 0; j < 8; j++)
#pragma unroll
            for (int k = 0; k < 4; k++) f.c[i][j][k] = 0.0f;

    int ti = 0;
    while (ti < nt) {
        // -------- segment: tiles ti..ti+Lt-1 share this bi --------
        int Lt = nt - ti;
        if (Lt > NTILE - bj) Lt = NTILE - bj;
        int ML = 4 * Lt;

        __syncthreads();   // previous segment fully consumed (A safe to overwrite)

        // Prologue: A (full K) + B chunk0 in group0; B chunk1 in group1.
        const char* gA = base + (size_t)bi * 65536;
        const char* gB0 = base + (size_t)bj * 65536;
#pragma unroll
        for (int o = 0; o < 16; o++) CP16(sb + doffA[o], gA + soffA[o]);
#pragma unroll
        for (int o = 0; o < 4; o++) CP16(sbB + doffB[o], gB0 + soffB[o]);
        CP_COMMIT();
#pragma unroll
        for (int o = 0; o < 4; o++)
            CP16(sbB + BCHUNK + doffB[o], gB0 + 128 + soffB[o]);
        CP_COMMIT();

        for (int m = 0; m < ML; m++) {
            if (m < ML - 1) { CP_WAIT(1); } else { CP_WAIT(0); }
            __syncthreads();

            // Prefetch B chunk m+2 (within segment) into stage (m+2)%3.
            int pf = m + 2;
            if (pf < ML) {
                int kc = pf & 3;
                const char* b = base + (size_t)(bj + (pf >> 2)) * 65536 + kc * 128;
                uint32_t d0 = sbB + (uint32_t)((pf % 3) * BCHUNK);
#pragma unroll
                for (int o = 0; o < 4; o++) CP16(d0 + doffB[o], b + soffB[o]);
                CP_COMMIT();
            }

            int kc = m & 3;
            compute_chunk(sb + (uint32_t)(kc * BCHUNK),
                          sbB + (uint32_t)((m % 3) * BCHUNK),
                          warp_m, warp_n, lane, f);

            if (kc == 3) {
                // ---- Epilogue for tile (bi, bj + (m>>2)) ----
                int bjc = bj + (m >> 2);
                bool diag = (bi == bjc);
                int r0 = lane >> 2;
                int cq = (lane & 3) * 2;
                float rowsum[2][2] = {{0.f, 0.f}, {0.f, 0.f}};
                float colsum[8][2];
#pragma unroll
                for (int j = 0; j < 8; j++) { colsum[j][0] = 0.f; colsum[j][1] = 0.f; }

#pragma unroll
                for (int i = 0; i < 2; i++) {
                    int grA = bi * 128 + warp_m * 32 + i * 16 + r0;
#pragma unroll
                    for (int j = 0; j < 8; j++) {
                        int gc = bjc * 128 + warp_n * 64 + j * 8 + cq;
                        float e0 = ex2(fmaf(f.c[i][j][0], SH2, -SH2));
                        float e1 = ex2(fmaf(f.c[i][j][1], SH2, -SH2));
                        float e2 = ex2(fmaf(f.c[i][j][2], SH2, -SH2));
                        float e3 = ex2(fmaf(f.c[i][j][3], SH2, -SH2));
                        if (diag) {
                            if (grA == gc)         e0 = 0.0f;
                            if (grA == gc + 1)     e1 = 0.0f;
                            if (grA + 8 == gc)     e2 = 0.0f;
                            if (grA + 8 == gc + 1) e3 = 0.0f;
                        }
                        rowsum[i][0] += e0 + e1;
                        rowsum[i][1] += e2 + e3;
                        colsum[j][0] += e0 + e2;
                        colsum[j][1] += e1 + e3;
                    }
                }

#pragma unroll
                for (int i = 0; i < 2; i++)
#pragma unroll
                    for (int h = 0; h < 2; h++) {
                        rowsum[i][h] += __shfl_xor_sync(0xffffffffu, rowsum[i][h], 1);
                        rowsum[i][h] += __shfl_xor_sync(0xffffffffu, rowsum[i][h], 2);
                    }
                if ((lane & 3) == 0) {
#pragma unroll
                    for (int i = 0; i < 2; i++) {
                        int gr = bi * 128 + warp_m * 32 + i * 16 + r0;
                        atomicAdd(&g_acc[gr], rowsum[i][0]);
                        atomicAdd(&g_acc[gr + 8], rowsum[i][1]);
                    }
                }
                if (!diag) {
#pragma unroll
                    for (int j = 0; j < 8; j++)
#pragma unroll
                        for (int h = 0; h < 2; h++) {
                            colsum[j][h] += __shfl_xor_sync(0xffffffffu, colsum[j][h], 4);
                            colsum[j][h] += __shfl_xor_sync(0xffffffffu, colsum[j][h], 8);
                            colsum[j][h] += __shfl_xor_sync(0xffffffffu, colsum[j][h], 16);
                        }
                    if (lane < 4) {
#pragma unroll
                        for (int j = 0; j < 8; j++) {
                            int gc = bjc * 128 + warp_n * 64 + j * 8 + lane * 2;
                            atomicAdd(&g_acc[gc], colsum[j][0]);
                            atomicAdd(&g_acc[gc + 1], colsum[j][1]);
                        }
                    }
                }
                // reset accumulators for next tile
#pragma unroll
                for (int i = 0; i < 2; i++)
#pragma unroll
                    for (int j = 0; j < 8; j++)
#pragma unroll
                        for (int k = 0; k < 4; k++) f.c[i][j][k] = 0.0f;
            }
        }

        // advance to next segment
        ti += Lt;
        bj += Lt;
        if (bj == NTILE) { bi++; bj = bi; }
    }

    // ---- Grid-completion handoff: last CTA computes the loss. ----
    __threadfence();
    __syncthreads();
    __shared__ unsigned s_ticket;
    if (t == 0) s_ticket = atomicAdd(&g_done, 1u);
    __syncthreads();
    if (s_ticket == NCTA - 1) {
        float s = 0.0f;
        for (int i = t; i < M_TOT; i += 256)
            s += INV_T + __logf(g_acc[i]) - g_pos[i & (NS - 1)] * INV_T;
#pragma unroll
        for (int off = 16; off; off >>= 1)
            s += __shfl_xor_sync(0xffffffffu, s, off);
        __shared__ float ws[8];
        if (lane == 0) ws[wid] = s;
        __syncthreads();
        if (t == 0) {
            float tot = 0.0f;
#pragma unroll
            for (int k = 0; k < 8; k++) tot += ws[k];
            out[0] = tot * (1.0f / (float)M_TOT);
            g_done = 0;   // reset for graph replay determinism
        }
    }
}

// ---------------------------------------------------------------------------
extern "C" void kernel_launch(void* const* d_in, const int* in_sizes, int n_in,
                              void* d_out, int out_size) {
    (void)in_sizes; (void)n_in; (void)out_size;
    const float* z1 = (const float*)d_in[0];
    const float* z2 = (const float*)d_in[1];
    float* out = (float*)d_out;

    cudaFuncSetAttribute(sim_kernel, cudaFuncAttributeMaxDynamicSharedMemorySize, SMEM_TOTAL);

    normpos_kernel<<<NS / 8, 256>>>(z1, z2);
    sim_kernel<<<NCTA, 256, SMEM_TOTAL>>>(out);
}

// round 14
// speedup vs baseline: 1.1290x; 1.0004x over previous
#include <cuda_runtime.h>
#include <cuda_bf16.h>
#include <math.h>
#include <cstdint>

#define M_TOT 8192
#define NS    4096
#define DDIM  256
#define INV_T 14.285714285714286f    // 1 / 0.07
#define SH2   20.60992915555662f     // log2(e) / 0.07  (prefolded exp2 scale)

#define NTILE 64                      // 64 row-blocks of 128
#define NCTA  304                     // 2 per SM x 152 SMs (GB300)

// sim kernel: 128x128 tile. A tile resident (full K=256, 4 chunk-blocks of 16KB);
// B streamed in 16KB chunks (64 cols) through a 3-stage ring.
#define BCHUNK     16384
#define A_BYTES    65536                       // 4 * 16KB chunk-blocks
#define SMEM_TOTAL (A_BYTES + 3 * BCHUNK)      // 114688 B (112 KB) -> 2 CTAs/SM

// Scratch (allocation-free rule: __device__ globals)
__device__ __align__(16) __nv_bfloat16 g_featb[M_TOT * DDIM];  // 4 MB
__device__ float g_acc[M_TOT];
__device__ float g_pos[NS];
__device__ unsigned g_done = 0;

// ---------------- helpers ----------------
__device__ __forceinline__ uint32_t smem_u32(const void* p) {
    uint32_t a;
    asm("{ .reg .u64 t; cvta.to.shared.u64 t, %1; cvt.u32.u64 %0, t; }" : "=r"(a) : "l"(p));
    return a;
}
#define CP16(dst, src) \
    asm volatile("cp.async.cg.shared.global [%0], [%1], 16;" :: "r"(dst), "l"(src))
#define CP_COMMIT() asm volatile("cp.async.commit_group;" ::: "memory")
#define CP_WAIT(n)  asm volatile("cp.async.wait_group %0;" :: "n"(n) : "memory")

#define LDSM4(r0, r1, r2, r3, addr) \
    asm volatile("ldmatrix.sync.aligned.m8n8.x4.shared.b16 {%0,%1,%2,%3}, [%4];" \
                 : "=r"(r0), "=r"(r1), "=r"(r2), "=r"(r3) : "r"(addr))

#define MMA16816(c0, c1, c2, c3, a0, a1, a2, a3, b0, b1) \
    asm volatile("mma.sync.aligned.m16n8k16.row.col.f32.bf16.bf16.f32 " \
                 "{%0,%1,%2,%3},{%4,%5,%6,%7},{%8,%9},{%0,%1,%2,%3};" \
                 : "+f"(c0), "+f"(c1), "+f"(c2), "+f"(c3) \
                 : "r"(a0), "r"(a1), "r"(a2), "r"(a3), "r"(b0), "r"(b1))

__device__ __forceinline__ float ex2(float x) {
    float r;
    asm("ex2.approx.ftz.f32 %0, %1;" : "=f"(r) : "f"(x));
    return r;
}

// ---------------------------------------------------------------------------
// Kernel 1: fused clean + L2-normalize + positive-pair dot (one warp per pair).
// ---------------------------------------------------------------------------
__global__ __launch_bounds__(256) void normpos_kernel(
    const float* __restrict__ z1, const float* __restrict__ z2) {
    int w = threadIdx.x >> 5, lane = threadIdx.x & 31;
    int j = blockIdx.x * 8 + w;
    const float* s1 = z1 + (size_t)j * DDIM + lane * 8;
    const float* s2 = z2 + (size_t)j * DDIM + lane * 8;
    float4 a0 = *(const float4*)s1, a1 = *(const float4*)(s1 + 4);
    float4 b0 = *(const float4*)s2, b1 = *(const float4*)(s2 + 4);
    float x1[8] = {a0.x, a0.y, a0.z, a0.w, a1.x, a1.y, a1.z, a1.w};
    float x2[8] = {b0.x, b0.y, b0.z, b0.w, b1.x, b1.y, b1.z, b1.w};
    float ss1 = 0.f, ss2 = 0.f, sd = 0.f;
#pragma unroll
    for (int i = 0; i < 8; i++) {
        if (!isfinite(x1[i])) x1[i] = 0.0f;
        if (!isfinite(x2[i])) x2[i] = 0.0f;
        ss1 = fmaf(x1[i], x1[i], ss1);
        ss2 = fmaf(x2[i], x2[i], ss2);
        sd  = fmaf(x1[i], x2[i], sd);
    }
#pragma unroll
    for (int off = 16; off; off >>= 1) {
        ss1 += __shfl_xor_sync(0xffffffffu, ss1, off);
        ss2 += __shfl_xor_sync(0xffffffffu, ss2, off);
        sd  += __shfl_xor_sync(0xffffffffu, sd, off);
    }
    float inv1 = 1.0f / fmaxf(sqrtf(ss1), 1e-12f);
    float inv2 = 1.0f / fmaxf(sqrtf(ss2), 1e-12f);
    __nv_bfloat162 o[4];
#pragma unroll
    for (int i = 0; i < 4; i++)
        o[i] = __floats2bfloat162_rn(x1[2 * i] * inv1, x1[2 * i + 1] * inv1);
    *(uint2*)(g_featb + (size_t)j * DDIM + lane * 8) = *(uint2*)&o[0];
    *(uint2*)(g_featb + (size_t)j * DDIM + lane * 8 + 4) = *(uint2*)&o[2];
#pragma unroll
    for (int i = 0; i < 4; i++)
        o[i] = __floats2bfloat162_rn(x2[2 * i] * inv2, x2[2 * i + 1] * inv2);
    *(uint2*)(g_featb + (size_t)(j + NS) * DDIM + lane * 8) = *(uint2*)&o[0];
    *(uint2*)(g_featb + (size_t)(j + NS) * DDIM + lane * 8 + 4) = *(uint2*)&o[2];
    if (lane == 0) {
        g_pos[j] = sd * inv1 * inv2;
        g_acc[j] = 0.0f;
        g_acc[j + NS] = 0.0f;
    }
}

// ---------------------------------------------------------------------------
// Kernel 2: persistent fused HMMA sim GEMM + exp + row/col sums + final loss.
// 304 persistent CTAs over 2080 upper-triangle 128x128 tiles (contiguous runs).
// A tile resident per bi-segment (64KB); B chunks (16KB) stream via 3-stage ring.
// Chunks 0-2: plain compute. Chunk 3: jj-major compute FUSED with the exp/sum
// epilogue so MUFU/FADD overlap the tensor pipe instead of idling it.
// Last CTA (ticket counter) computes the scalar loss inline.
// ---------------------------------------------------------------------------
struct Frag { float c[2][8][4]; };

__device__ __forceinline__ void compute_chunk(
    uint32_t abase, uint32_t bbase, int warp_m, int warp_n, int lane, Frag& f) {
    int lrow = lane & 15, khalf = lane >> 4;
#pragma unroll
    for (int ks = 0; ks < 4; ks++) {
        int segk = 2 * ks + khalf;
        uint32_t a0[4], a1[4];
        {
            int r = warp_m * 32 + lrow;
            LDSM4(a0[0], a0[1], a0[2], a0[3], abase + r * 128 + ((segk ^ (r & 7)) << 4));
            r += 16;
            LDSM4(a1[0], a1[1], a1[2], a1[3], abase + r * 128 + ((segk ^ (r & 7)) << 4));
        }
#pragma unroll
        for (int jj = 0; jj < 4; jj++) {
            int r = warp_n * 64 + jj * 16 + lrow;
            uint32_t b0, b1, b2, b3;
            LDSM4(b0, b1, b2, b3, bbase + r * 128 + ((segk ^ (r & 7)) << 4));
            MMA16816(f.c[0][jj*2][0], f.c[0][jj*2][1], f.c[0][jj*2][2], f.c[0][jj*2][3],
                     a0[0], a0[1], a0[2], a0[3], b0, b2);
            MMA16816(f.c[0][jj*2+1][0], f.c[0][jj*2+1][1], f.c[0][jj*2+1][2], f.c[0][jj*2+1][3],
                     a0[0], a0[1], a0[2], a0[3], b1, b3);
            MMA16816(f.c[1][jj*2][0], f.c[1][jj*2][1], f.c[1][jj*2][2], f.c[1][jj*2][3],
                     a1[0], a1[1], a1[2], a1[3], b0, b2);
            MMA16816(f.c[1][jj*2+1][0], f.c[1][jj*2+1][1], f.c[1][jj*2+1][2], f.c[1][jj*2+1][3],
                     a1[0], a1[1], a1[2], a1[3], b1, b3);
        }
    }
}

// exp + row/col partial sums for column block jj (accums complete for that jj).
__device__ __forceinline__ void epi_jj(
    Frag& f, int jj, int bi, int bjc, bool diag, int warp_m, int warp_n,
    int r0, int cq, float rowsum[2][2], float colsum[8][2]) {
#pragma unroll
    for (int i = 0; i < 2; i++) {
        int grA = bi * 128 + warp_m * 32 + i * 16 + r0;
#pragma unroll
        for (int jo = 0; jo < 2; jo++) {
            int j = jj * 2 + jo;
            int gc = bjc * 128 + warp_n * 64 + j * 8 + cq;
            float e0 = ex2(fmaf(f.c[i][j][0], SH2, -SH2));
            float e1 = ex2(fmaf(f.c[i][j][1], SH2, -SH2));
            float e2 = ex2(fmaf(f.c[i][j][2], SH2, -SH2));
            float e3 = ex2(fmaf(f.c[i][j][3], SH2, -SH2));
            if (diag) {
                if (grA == gc)         e0 = 0.0f;
                if (grA == gc + 1)     e1 = 0.0f;
                if (grA + 8 == gc)     e2 = 0.0f;
                if (grA + 8 == gc + 1) e3 = 0.0f;
            }
            rowsum[i][0] += e0 + e1;
            rowsum[i][1] += e2 + e3;
            colsum[j][0] += e0 + e2;
            colsum[j][1] += e1 + e3;
        }
    }
}

// Last chunk of a tile: jj-major compute with the epilogue software-pipelined
// one jj behind, so MUFU/FADD overlap the tensor pipe.
__device__ __forceinline__ void compute_chunk_fused(
    uint32_t abase, uint32_t bbase, int warp_m, int warp_n, int lane,
    Frag& f, int bi, int bjc, bool diag,
    int r0, int cq, float rowsum[2][2], float colsum[8][2]) {
    int lrow = lane & 15, khalf = lane >> 4;
#pragma unroll
    for (int jj = 0; jj < 4; jj++) {
        int rB = warp_n * 64 + jj * 16 + lrow;
#pragma unroll
        for (int ks = 0; ks < 4; ks++) {
            int segk = 2 * ks + khalf;
            uint32_t a0[4], a1[4];
            {
                int r = warp_m * 32 + lrow;
                LDSM4(a0[0], a0[1], a0[2], a0[3], abase + r * 128 + ((segk ^ (r & 7)) << 4));
                r += 16;
                LDSM4(a1[0], a1[1], a1[2], a1[3], abase + r * 128 + ((segk ^ (r & 7)) << 4));
            }
            uint32_t b0, b1, b2, b3;
            LDSM4(b0, b1, b2, b3, bbase + rB * 128 + ((segk ^ (rB & 7)) << 4));
            MMA16816(f.c[0][jj*2][0], f.c[0][jj*2][1], f.c[0][jj*2][2], f.c[0][jj*2][3],
                     a0[0], a0[1], a0[2], a0[3], b0, b2);
            MMA16816(f.c[0][jj*2+1][0], f.c[0][jj*2+1][1], f.c[0][jj*2+1][2], f.c[0][jj*2+1][3],
                     a0[0], a0[1], a0[2], a0[3], b1, b3);
            MMA16816(f.c[1][jj*2][0], f.c[1][jj*2][1], f.c[1][jj*2][2], f.c[1][jj*2][3],
                     a1[0], a1[1], a1[2], a1[3], b0, b2);
            MMA16816(f.c[1][jj*2+1][0], f.c[1][jj*2+1][1], f.c[1][jj*2+1][2], f.c[1][jj*2+1][3],
                     a1[0], a1[1], a1[2], a1[3], b1, b3);
        }
        if (jj > 0)   // epilogue for the previous jj overlaps this jj's MMAs
            epi_jj(f, jj - 1, bi, bjc, diag, warp_m, warp_n, r0, cq, rowsum, colsum);
    }
    epi_jj(f, 3, bi, bjc, diag, warp_m, warp_n, r0, cq, rowsum, colsum);
}

__global__ __launch_bounds__(256, 2) void sim_kernel(float* __restrict__ out) {
    extern __shared__ char smem[];
    uint32_t sb  = smem_u32(smem);        // A resident region (64 KB)
    uint32_t sbB = sb + A_BYTES;          // B ring (3 x 16 KB)
    int t = threadIdx.x, lane = t & 31, wid = t >> 5;
    int warp_m = wid & 3, warp_n = wid >> 2;
    int cta = blockIdx.x;

    // Contiguous tile range: first 256 CTAs get 7 tiles, rest get 6 (256*7+48*6=2080).
    int nt = 6 + (cta < 256 ? 1 : 0);
    int start = cta * 6 + (cta < 256 ? cta : 256);

    // Decode start tile (bi, bj) by integer walk over triangle rows.
    int bi = 0, rem = start;
    while (rem >= NTILE - bi) { rem -= NTILE - bi; bi++; }
    int bj = bi + rem;

    // Per-thread B-chunk offsets: 4 x 16B segments (1024 segs over 256 threads).
    uint32_t doffB[4]; int soffB[4];
#pragma unroll
    for (int o = 0; o < 4; o++) {
        int idx = t + o * 256;
        int r = idx >> 3, seg = idx & 7;
        doffB[o] = (uint32_t)(r * 128 + ((seg ^ (r & 7)) << 4));
        soffB[o] = r * 512 + seg * 16;
    }

    const char* base = (const char*)g_featb;

    Frag f;
#pragma unroll
    for (int i = 0; i < 2; i++)
#pragma unroll
        for (int j = 0; j < 8; j++)
#pragma unroll
            for (int k = 0; k < 4; k++) f.c[i][j][k] = 0.0f;

    int ti = 0;
    while (ti < nt) {
        // -------- segment: tiles ti..ti+Lt-1 share this bi --------
        int Lt = nt - ti;
        if (Lt > NTILE - bj) Lt = NTILE - bj;
        int ML = 4 * Lt;

        __syncthreads();   // previous segment fully consumed (A safe to overwrite)

        // Prologue: A (full K) + B chunk0 in group0; B chunk1 in group1.
        const char* gA = base + (size_t)bi * 65536;
        const char* gB0 = base + (size_t)bj * 65536;
#pragma unroll
        for (int o = 0; o < 16; o++) {
            int idx = t + o * 256;           // 0..4095 (cold path: computed inline)
            int ch = idx >> 10;
            int i1 = idx & 1023;
            int r = i1 >> 3, seg = i1 & 7;
            CP16(sb + (uint32_t)(ch * BCHUNK + r * 128 + ((seg ^ (r & 7)) << 4)),
                 gA + r * 512 + ch * 128 + seg * 16);
        }
#pragma unroll
        for (int o = 0; o < 4; o++) CP16(sbB + doffB[o], gB0 + soffB[o]);
        CP_COMMIT();
#pragma unroll
        for (int o = 0; o < 4; o++)
            CP16(sbB + BCHUNK + doffB[o], gB0 + 128 + soffB[o]);
        CP_COMMIT();

        for (int m = 0; m < ML; m++) {
            if (m < ML - 1) { CP_WAIT(1); } else { CP_WAIT(0); }
            __syncthreads();

            // Prefetch B chunk m+2 (within segment) into stage (m+2)%3.
            int pf = m + 2;
            if (pf < ML) {
                int kc2 = pf & 3;
                const char* b = base + (size_t)(bj + (pf >> 2)) * 65536 + kc2 * 128;
                uint32_t d0 = sbB + (uint32_t)((pf % 3) * BCHUNK);
#pragma unroll
                for (int o = 0; o < 4; o++) CP16(d0 + doffB[o], b + soffB[o]);
                CP_COMMIT();
            }

            int kc = m & 3;
            uint32_t abase = sb + (uint32_t)(kc * BCHUNK);
            uint32_t bbase = sbB + (uint32_t)((m % 3) * BCHUNK);

            if (kc < 3) {
                compute_chunk(abase, bbase, warp_m, warp_n, lane, f);
            } else {
                // ---- Last chunk fused with tile epilogue ----
                int bjc = bj + (m >> 2);
                bool diag = (bi == bjc);
                int r0 = lane >> 2;
                int cq = (lane & 3) * 2;
                float rowsum[2][2] = {{0.f, 0.f}, {0.f, 0.f}};
                float colsum[8][2];
#pragma unroll
                for (int j = 0; j < 8; j++) { colsum[j][0] = 0.f; colsum[j][1] = 0.f; }

                compute_chunk_fused(abase, bbase, warp_m, warp_n, lane, f,
                                    bi, bjc, diag, r0, cq, rowsum, colsum);

#pragma unroll
                for (int i = 0; i < 2; i++)
#pragma unroll
                    for (int h = 0; h < 2; h++) {
                        rowsum[i][h] += __shfl_xor_sync(0xffffffffu, rowsum[i][h], 1);
                        rowsum[i][h] += __shfl_xor_sync(0xffffffffu, rowsum[i][h], 2);
                    }
                if ((lane & 3) == 0) {
#pragma unroll
                    for (int i = 0; i < 2; i++) {
                        int gr = bi * 128 + warp_m * 32 + i * 16 + r0;
                        atomicAdd(&g_acc[gr], rowsum[i][0]);
                        atomicAdd(&g_acc[gr + 8], rowsum[i][1]);
                    }
                }
                if (!diag) {
#pragma unroll
                    for (int j = 0; j < 8; j++)
#pragma unroll
                        for (int h = 0; h < 2; h++) {
                            colsum[j][h] += __shfl_xor_sync(0xffffffffu, colsum[j][h], 4);
                            colsum[j][h] += __shfl_xor_sync(0xffffffffu, colsum[j][h], 8);
                            colsum[j][h] += __shfl_xor_sync(0xffffffffu, colsum[j][h], 16);
                        }
                    if (lane < 4) {
#pragma unroll
                        for (int j = 0; j < 8; j++) {
                            int gc = bjc * 128 + warp_n * 64 + j * 8 + lane * 2;
                            atomicAdd(&g_acc[gc], colsum[j][0]);
                            atomicAdd(&g_acc[gc + 1], colsum[j][1]);
                        }
                    }
                }
                // reset accumulators for next tile
#pragma unroll
                for (int i = 0; i < 2; i++)
#pragma unroll
                    for (int j = 0; j < 8; j++)
#pragma unroll
                        for (int k = 0; k < 4; k++) f.c[i][j][k] = 0.0f;
            }
        }

        // advance to next segment
        ti += Lt;
        bj += Lt;
        if (bj == NTILE) { bi++; bj = bi; }
    }

    // ---- Grid-completion handoff: last CTA computes the loss. ----
    __threadfence();
    __syncthreads();
    __shared__ unsigned s_ticket;
    if (t == 0) s_ticket = atomicAdd(&g_done, 1u);
    __syncthreads();
    if (s_ticket == NCTA - 1) {
        float s = 0.0f;
        for (int i = t; i < M_TOT; i += 256)
            s += INV_T + __logf(g_acc[i]) - g_pos[i & (NS - 1)] * INV_T;
#pragma unroll
        for (int off = 16; off; off >>= 1)
            s += __shfl_xor_sync(0xffffffffu, s, off);
        __shared__ float ws[8];
        if (lane == 0) ws[wid] = s;
        __syncthreads();
        if (t == 0) {
            float tot = 0.0f;
#pragma unroll
            for (int k = 0; k < 8; k++) tot += ws[k];
            out[0] = tot * (1.0f / (float)M_TOT);
            g_done = 0;   // reset for graph replay determinism
        }
    }
}

// ---------------------------------------------------------------------------
extern "C" void kernel_launch(void* const* d_in, const int* in_sizes, int n_in,
                              void* d_out, int out_size) {
    (void)in_sizes; (void)n_in; (void)out_size;
    const float* z1 = (const float*)d_in[0];
    const float* z2 = (const float*)d_in[1];
    float* out = (float*)d_out;

    cudaFuncSetAttribute(sim_kernel, cudaFuncAttributeMaxDynamicSharedMemorySize, SMEM_TOTAL);

    normpos_kernel<<<NS / 8, 256>>>(z1, z2);
    sim_kernel<<<NCTA, 256, SMEM_TOTAL>>>(out);
}